// round 11
// baseline (speedup 1.0000x reference)
#include <cuda_runtime.h>
#include <cuda_fp16.h>
#include <cstdint>

// Problem constants
#define BDIM  4096
#define TDIM  32
#define KDIM  16
#define DDIM  512
#define HDIM  1024   // = 2*D
#define H2DIM 2048   // = 2*H

// NOTE: harness PTX target is compute_103 (no 'a') -> tcgen05/TMEM rejected.
// Legacy mma.sync HMMA is the tensor path. All GEMMs single-pass fp16.

// ---------------------------------------------------------------------------
// Scratch (device globals: allocation-free rule)
// ---------------------------------------------------------------------------
__device__ float E1_buf[BDIM * HDIM];
__device__ float E2_buf[BDIM * H2DIM];
__device__ float e_buf[BDIM * TDIM];

__device__ __half Xh_buf[BDIM * TDIM * DDIM];
__device__ __half Gh_buf[BDIM * KDIM * DDIM];
__device__ __half W1h_buf[2 * DDIM * HDIM];   // full W1 (1024 x 1024)
__device__ __half M1h_buf[2 * DDIM * H2DIM];  // full M1 (1024 x 2048)
__device__ __half ghh_buf[BDIM * DDIM];
__device__ __half xhh_buf[BDIM * DDIM];

// ---------------------------------------------------------------------------
// PTX helpers
// ---------------------------------------------------------------------------
__device__ __forceinline__ void cp16(uint32_t dst, const void* src) {
    asm volatile("cp.async.cg.shared.global [%0], [%1], 16;\n"
                 :: "r"(dst), "l"(src) : "memory");
}
__device__ __forceinline__ void cp_commit() {
    asm volatile("cp.async.commit_group;\n" ::: "memory");
}
__device__ __forceinline__ void cp_wait1() {
    asm volatile("cp.async.wait_group 1;\n" ::: "memory");
}
__device__ __forceinline__ void ldsm_x4(unsigned& d0, unsigned& d1, unsigned& d2,
                                        unsigned& d3, uint32_t addr) {
    asm volatile("ldmatrix.sync.aligned.m8n8.x4.shared.b16 {%0,%1,%2,%3}, [%4];\n"
                 : "=r"(d0), "=r"(d1), "=r"(d2), "=r"(d3) : "r"(addr));
}
__device__ __forceinline__ void ldsm_x4_t(unsigned& d0, unsigned& d1, unsigned& d2,
                                          unsigned& d3, uint32_t addr) {
    asm volatile("ldmatrix.sync.aligned.m8n8.x4.trans.shared.b16 {%0,%1,%2,%3}, [%4];\n"
                 : "=r"(d0), "=r"(d1), "=r"(d2), "=r"(d3) : "r"(addr));
}
__device__ __forceinline__ void mma16816(float c[4], const unsigned a[4], const unsigned b[2]) {
    asm volatile(
        "mma.sync.aligned.m16n8k16.row.col.f32.f16.f16.f32 "
        "{%0,%1,%2,%3}, {%4,%5,%6,%7}, {%8,%9}, {%0,%1,%2,%3};\n"
        : "+f"(c[0]), "+f"(c[1]), "+f"(c[2]), "+f"(c[3])
        : "r"(a[0]), "r"(a[1]), "r"(a[2]), "r"(a[3]), "r"(b[0]), "r"(b[1]));
}

// ---------------------------------------------------------------------------
// convert-only: hi = fp16(x)
// ---------------------------------------------------------------------------
__global__ void conv_fp16_kernel(const float* __restrict__ src,
                                 __half* __restrict__ hi)
{
    int i = blockIdx.x * blockDim.x + threadIdx.x;
    float4 v = ((const float4*)src)[i];
    __half h[4];
    h[0] = __float2half_rn(v.x); h[1] = __float2half_rn(v.y);
    h[2] = __float2half_rn(v.z); h[3] = __float2half_rn(v.w);
    ((uint2*)hi)[i] = *(uint2*)h;
}

// ---------------------------------------------------------------------------
// fused: G -> Gh (fp16) AND ghh = fp16(mean_k G)   (single read of G)
// one thread per float4 chunk of (b, d): loops the 16 k rows.
// ---------------------------------------------------------------------------
__global__ void gconv_gmean_kernel(const float* __restrict__ G,
                                   __half* __restrict__ Gh,
                                   __half* __restrict__ ghh)
{
    int idx = blockIdx.x * blockDim.x + threadIdx.x;   // over B * (D/4)
    int b  = idx >> 7;          // 128 chunks per b
    int ch = idx & 127;
    const float4* gp = (const float4*)(G + (size_t)b * KDIM * DDIM + ch * 4);
    float4 acc = make_float4(0.f, 0.f, 0.f, 0.f);
#pragma unroll
    for (int k = 0; k < KDIM; k++) {
        float4 v = gp[k * (DDIM / 4)];
        __half h[4];
        h[0] = __float2half_rn(v.x); h[1] = __float2half_rn(v.y);
        h[2] = __float2half_rn(v.z); h[3] = __float2half_rn(v.w);
        ((uint2*)Gh)[((size_t)b * KDIM * DDIM + (size_t)k * DDIM) / 4 + ch] = *(uint2*)h;
        acc.x += v.x; acc.y += v.y; acc.z += v.z; acc.w += v.w;
    }
    const float inv = 1.0f / KDIM;
    __half m[4];
    m[0] = __float2half_rn(acc.x * inv); m[1] = __float2half_rn(acc.y * inv);
    m[2] = __float2half_rn(acc.z * inv); m[3] = __float2half_rn(acc.w * inv);
    ((uint2*)ghh)[idx] = *(uint2*)m;
}

// ---------------------------------------------------------------------------
// fp16 tensor-core GEMM. BM=128, BN=128, BK=64, 4 warps (2m x 2n),
// warp tile 64x64 (128 accum regs/thread). 3-stage cp.async pipeline,
// single __syncthreads per k-tile (8 k-tiles over K=512).
// REDUCE=true : out[row] = sum_n relu(acc + Eb[row>>RPB_SHIFT, n]) * wvec[n] (+sc)
//               grid = (M/128), loops all N tiles internally.
// REDUCE=false: out[row,col] = acc + bias[col]; grid = (M/128, N/128).
// ---------------------------------------------------------------------------
constexpr int ASZ = 128 * 72 * 2;     // one A stage (bytes), row stride 72 halves
constexpr int BSZ = 64 * 136 * 2;     // one B stage (bytes), row stride 136 halves
constexpr int SMEM_BYTES = 3 * ASZ + 3 * BSZ + 128 * 2 * 4;
constexpr int NKT = DDIM / 64;        // 8 k-tiles

template <int RPB_SHIFT, bool REDUCE>
__global__ void __launch_bounds__(128, 2) mma_gemm(
    const __half* __restrict__ Ah,
    const __half* __restrict__ Bh,
    const float* __restrict__ EbOrBias,
    const float* __restrict__ wvec,
    const float* __restrict__ addsc,
    float* __restrict__ out,
    int N)
{
    extern __shared__ __align__(16) char smraw[];
    float* red = (float*)(smraw + 3 * ASZ + 3 * BSZ);   // [128][2]

    const int tid  = threadIdx.x;
    const int lane = tid & 31;
    const int wid  = tid >> 5;
    const int warp_m = wid & 1;       // 2 warps in M
    const int warp_n = wid >> 1;      // 2 warps in N
    const int lq = lane >> 2, lr = lane & 3;
    const int rb = blockIdx.x * 128;

    const uint32_t uS = (uint32_t)__cvta_generic_to_shared(smraw);
    const uint32_t uA = uS;
    const uint32_t uB = uS + 3 * ASZ;

    // ldmatrix per-lane address components
    const uint32_t a_frag_off =
        (uint32_t)(((warp_m * 64 + (lane & 15)) * 72 + ((lane & 16) >> 1)) * 2);
    const uint32_t b_frag_off =
        (uint32_t)(((lane & 15) * 136 + warp_n * 64 + ((lane & 16) >> 1)) * 2);

    float rs[4][2] = {};
    const int ntiles = REDUCE ? (N >> 7) : 1;

    for (int nt = 0; nt < ntiles; nt++) {
        const int cb = REDUCE ? (nt << 7) : ((int)blockIdx.y << 7);

        float c[4][8][4] = {};

        // staging: A 128x64 halves (8 chunks/thread), B 64x128 (8 chunks/thread)
        auto stage = [&](int buf, int kt) {
            const int koff = kt << 6;
            const uint32_t adst0 = uA + (uint32_t)(buf * ASZ);
            const uint32_t bdst0 = uB + (uint32_t)(buf * BSZ);
#pragma unroll
            for (int cc = 0; cc < 8; cc++) {
                int cid = tid + cc * 128;
                int am = cid >> 3, ak = (cid & 7) << 3;
                cp16(adst0 + (uint32_t)((am * 72 + ak) * 2),
                     Ah + (size_t)(rb + am) * DDIM + koff + ak);
                int bk = cid >> 4, bn = (cid & 15) << 3;
                cp16(bdst0 + (uint32_t)((bk * 136 + bn) * 2),
                     Bh + (size_t)(koff + bk) * N + cb + bn);
            }
        };

        stage(0, 0); cp_commit();
        stage(1, 1); cp_commit();

        for (int kt = 0; kt < NKT; kt++) {
            cp_wait1();
            __syncthreads();
            if (kt + 2 < NKT) stage((kt + 2) % 3, kt + 2);
            cp_commit();

            const int buf = kt % 3;
            const uint32_t Ahb = uA + (uint32_t)(buf * ASZ) + a_frag_off;
            const uint32_t Bhb = uB + (uint32_t)(buf * BSZ) + b_frag_off;

#pragma unroll
            for (int kk = 0; kk < 64; kk += 16) {
                unsigned ah[4][4], bh[8][2];
#pragma unroll
                for (int mi = 0; mi < 4; mi++)
                    ldsm_x4(ah[mi][0], ah[mi][1], ah[mi][2], ah[mi][3],
                            Ahb + (uint32_t)((mi * 16 * 72 + kk) * 2));
#pragma unroll
                for (int g = 0; g < 4; g++)
                    ldsm_x4_t(bh[2*g][0], bh[2*g][1], bh[2*g+1][0], bh[2*g+1][1],
                              Bhb + (uint32_t)((kk * 136 + g * 16) * 2));
#pragma unroll
                for (int mi = 0; mi < 4; mi++)
#pragma unroll
                    for (int ni = 0; ni < 8; ni++)
                        mma16816(c[mi][ni], ah[mi], bh[ni]);
            }
        }
        __syncthreads();   // protect stage buffers before next nt prologue

        if (REDUCE) {
            // fused epilogue: relu(acc + Eb) . wvec
#pragma unroll
            for (int mi = 0; mi < 4; mi++) {
                int row0 = rb + warp_m * 64 + mi * 16 + lq;
                int row1 = row0 + 8;
                const float* Eb0 = EbOrBias + (size_t)(row0 >> RPB_SHIFT) * N;
                const float* Eb1 = EbOrBias + (size_t)(row1 >> RPB_SHIFT) * N;
#pragma unroll
                for (int ni = 0; ni < 8; ni++) {
                    int col = cb + warp_n * 64 + ni * 8 + lr * 2;
                    float2 e0 = *(const float2*)&Eb0[col];
                    float2 e1 = *(const float2*)&Eb1[col];
                    float2 wv = *(const float2*)&wvec[col];
                    rs[mi][0] += fmaxf(c[mi][ni][0] + e0.x, 0.f) * wv.x
                               + fmaxf(c[mi][ni][1] + e0.y, 0.f) * wv.y;
                    rs[mi][1] += fmaxf(c[mi][ni][2] + e1.x, 0.f) * wv.x
                               + fmaxf(c[mi][ni][3] + e1.y, 0.f) * wv.y;
                }
            }
        } else {
            // plain store epilogue: C = acc + bias
#pragma unroll
            for (int mi = 0; mi < 4; mi++) {
                int row0 = rb + warp_m * 64 + mi * 16 + lq;
                int row1 = row0 + 8;
#pragma unroll
                for (int ni = 0; ni < 8; ni++) {
                    int col = cb + warp_n * 64 + ni * 8 + lr * 2;
                    float2 bv = *(const float2*)&EbOrBias[col];
                    float2 o0, o1;
                    o0.x = c[mi][ni][0] + bv.x; o0.y = c[mi][ni][1] + bv.y;
                    o1.x = c[mi][ni][2] + bv.x; o1.y = c[mi][ni][3] + bv.y;
                    *(float2*)&out[(size_t)row0 * N + col] = o0;
                    *(float2*)&out[(size_t)row1 * N + col] = o1;
                }
            }
        }
    }

    if (REDUCE) {
        // reduce across the 4 lanes sharing each row, then across warp_n
#pragma unroll
        for (int mi = 0; mi < 4; mi++)
#pragma unroll
            for (int h = 0; h < 2; h++) {
                float s = rs[mi][h];
                s += __shfl_xor_sync(0xffffffffu, s, 1);
                s += __shfl_xor_sync(0xffffffffu, s, 2);
                if (lr == 0)
                    red[(warp_m * 64 + mi * 16 + h * 8 + lq) * 2 + warp_n] = s;
            }
        __syncthreads();
        {
            float addv = addsc ? *addsc : 0.f;
            out[rb + tid] = red[tid * 2 + 0] + red[tid * 2 + 1] + addv;
        }
    }
}

// ---------------------------------------------------------------------------
// K4: per-b softmax over T=32 then x_hat = sum_t alpha_t * Xh[b,t,:] -> fp16
// ---------------------------------------------------------------------------
__global__ void softmax_xhat_kernel(const float* __restrict__ e,
                                    const __half* __restrict__ Xh,
                                    __half* __restrict__ xh)
{
    int b = blockIdx.x;
    __shared__ float alpha[TDIM];
    int tid = threadIdx.x;   // 128 threads
    if (tid < 32) {
        float v = e[b * TDIM + tid];
        float m = v;
#pragma unroll
        for (int off = 16; off >= 1; off >>= 1)
            m = fmaxf(m, __shfl_xor_sync(0xffffffffu, m, off));
        float ex = __expf(v - m);
        float s = ex;
#pragma unroll
        for (int off = 16; off >= 1; off >>= 1)
            s += __shfl_xor_sync(0xffffffffu, s, off);
        alpha[tid] = ex / s;
    }
    __syncthreads();
    const __half* Xb = Xh + (size_t)b * TDIM * DDIM + tid * 4;
    float s0 = 0.f, s1 = 0.f, s2 = 0.f, s3 = 0.f;
#pragma unroll
    for (int t = 0; t < TDIM; t++) {
        uint2 raw = *(const uint2*)&Xb[t * DDIM];
        __half2 p0 = *(__half2*)&raw.x;
        __half2 p1 = *(__half2*)&raw.y;
        float a = alpha[t];
        s0 += a * __low2float(p0);  s1 += a * __high2float(p0);
        s2 += a * __low2float(p1);  s3 += a * __high2float(p1);
    }
    __half hh[4];
    hh[0] = __float2half_rn(s0); hh[1] = __float2half_rn(s1);
    hh[2] = __float2half_rn(s2); hh[3] = __float2half_rn(s3);
    ((uint2*)xh)[((size_t)b * DDIM + tid * 4) >> 2] = *(uint2*)hh;
}

// ---------------------------------------------------------------------------
extern "C" void kernel_launch(void* const* d_in, const int* in_sizes, int n_in,
                              void* d_out, int out_size)
{
    const float* X  = (const float*)d_in[0];
    const float* G  = (const float*)d_in[1];
    const float* W1 = (const float*)d_in[2];
    const float* b1 = (const float*)d_in[3];
    const float* w2 = (const float*)d_in[4];
    // d_in[5] = b2: softmax shift-invariant, unused
    const float* M1 = (const float*)d_in[6];
    const float* c1 = (const float*)d_in[7];
    const float* m2 = (const float*)d_in[8];
    const float* c2 = (const float*)d_in[9];
    float* out = (float*)d_out;

    float *E1, *E2, *ebuf;
    cudaGetSymbolAddress((void**)&E1,   E1_buf);
    cudaGetSymbolAddress((void**)&E2,   E2_buf);
    cudaGetSymbolAddress((void**)&ebuf, e_buf);

    __half *Xh, *Gh, *W1h, *M1h, *ghh, *xhh;
    cudaGetSymbolAddress((void**)&Xh,  Xh_buf);
    cudaGetSymbolAddress((void**)&Gh,  Gh_buf);
    cudaGetSymbolAddress((void**)&W1h, W1h_buf);
    cudaGetSymbolAddress((void**)&M1h, M1h_buf);
    cudaGetSymbolAddress((void**)&ghh, ghh_buf);
    cudaGetSymbolAddress((void**)&xhh, xhh_buf);

    cudaFuncSetAttribute((const void*)mma_gemm<5, true>,
                         cudaFuncAttributeMaxDynamicSharedMemorySize, SMEM_BYTES);
    cudaFuncSetAttribute((const void*)mma_gemm<4, true>,
                         cudaFuncAttributeMaxDynamicSharedMemorySize, SMEM_BYTES);
    cudaFuncSetAttribute((const void*)mma_gemm<0, false>,
                         cudaFuncAttributeMaxDynamicSharedMemorySize, SMEM_BYTES);

    // [0] convert X -> fp16
    conv_fp16_kernel<<<(BDIM * TDIM * DDIM / 4) / 256, 256>>>(X, Xh);
    // [1] convert W1 -> fp16
    conv_fp16_kernel<<<(2 * DDIM * HDIM / 4) / 256, 256>>>(W1, W1h);
    // [2] fused: G -> Gh, ghh = mean_k G (single read of G)
    gconv_gmean_kernel<<<(BDIM * DDIM / 4) / 256, 256>>>(G, Gh, ghh);
    // [3] K2: E1 = g_hat @ W1[:512] + b1   (4096 x 1024)
    mma_gemm<0, false><<<dim3(BDIM / 128, HDIM / 128), 128, SMEM_BYTES>>>(
        ghh, W1h, b1, nullptr, nullptr, E1, HDIM);
    // [4] convert M1 -> fp16
    conv_fp16_kernel<<<(2 * DDIM * H2DIM / 4) / 256, 256>>>(M1, M1h);
    // [5] K3: e[b,t] = sum_h relu( X@W1[512:] + E1 ) * w2   (M = 131072)
    mma_gemm<5, true><<<(BDIM * TDIM) / 128, 128, SMEM_BYTES>>>(
        Xh, W1h + (size_t)DDIM * HDIM, E1, w2, nullptr, ebuf, HDIM);
    // [6] softmax over T + x_hat -> fp16
    softmax_xhat_kernel<<<BDIM, 128>>>(ebuf, Xh, xhh);
    // [7] K5: E2 = x_hat @ M1[:512] + c1   (4096 x 2048)
    mma_gemm<0, false><<<dim3(BDIM / 128, H2DIM / 128), 128, SMEM_BYTES>>>(
        xhh, M1h, c1, nullptr, nullptr, E2, H2DIM);
    // [8] K6: logits = sum_j relu( G@M1[512:] + E2 ) * m2 + c2  (M = 65536)
    mma_gemm<4, true><<<(BDIM * KDIM) / 128, 128, SMEM_BYTES>>>(
        Gh, M1h + (size_t)DDIM * H2DIM, E2, m2, c2, out, H2DIM);
}

// round 12
// speedup vs baseline: 1.4282x; 1.4282x over previous
#include <cuda_runtime.h>
#include <cuda_fp16.h>
#include <cstdint>

// Problem constants
#define BDIM  4096
#define TDIM  32
#define KDIM  16
#define DDIM  512
#define HDIM  1024   // = 2*D
#define H2DIM 2048   // = 2*H

// NOTE: harness PTX target is compute_103 (no 'a') -> tcgen05/TMEM rejected.
// Legacy mma.sync HMMA is the tensor path. All GEMMs single-pass fp16.
// Operating point (R11 lesson): 256 thr/CTA, 2 CTAs/SM, 128 regs -> 16 warps/SM.

// ---------------------------------------------------------------------------
// Scratch (device globals: allocation-free rule)
// ---------------------------------------------------------------------------
__device__ float E1_buf[BDIM * HDIM];
__device__ float E2_buf[BDIM * H2DIM];
__device__ float e_buf[BDIM * TDIM];

__device__ __half Xh_buf[BDIM * TDIM * DDIM];
__device__ __half Gh_buf[BDIM * KDIM * DDIM];
__device__ __half W1h_buf[2 * DDIM * HDIM];   // full W1 (1024 x 1024)
__device__ __half M1h_buf[2 * DDIM * H2DIM];  // full M1 (1024 x 2048)
__device__ __half ghh_buf[BDIM * DDIM];
__device__ __half xhh_buf[BDIM * DDIM];

// ---------------------------------------------------------------------------
// PTX helpers
// ---------------------------------------------------------------------------
__device__ __forceinline__ void cp16(uint32_t dst, const void* src) {
    asm volatile("cp.async.cg.shared.global [%0], [%1], 16;\n"
                 :: "r"(dst), "l"(src) : "memory");
}
__device__ __forceinline__ void cp_commit() {
    asm volatile("cp.async.commit_group;\n" ::: "memory");
}
__device__ __forceinline__ void cp_wait1() {
    asm volatile("cp.async.wait_group 1;\n" ::: "memory");
}
__device__ __forceinline__ void ldsm_x4(unsigned& d0, unsigned& d1, unsigned& d2,
                                        unsigned& d3, uint32_t addr) {
    asm volatile("ldmatrix.sync.aligned.m8n8.x4.shared.b16 {%0,%1,%2,%3}, [%4];\n"
                 : "=r"(d0), "=r"(d1), "=r"(d2), "=r"(d3) : "r"(addr));
}
__device__ __forceinline__ void ldsm_x4_t(unsigned& d0, unsigned& d1, unsigned& d2,
                                          unsigned& d3, uint32_t addr) {
    asm volatile("ldmatrix.sync.aligned.m8n8.x4.trans.shared.b16 {%0,%1,%2,%3}, [%4];\n"
                 : "=r"(d0), "=r"(d1), "=r"(d2), "=r"(d3) : "r"(addr));
}
__device__ __forceinline__ void mma16816(float c[4], const unsigned a[4], const unsigned b[2]) {
    asm volatile(
        "mma.sync.aligned.m16n8k16.row.col.f32.f16.f16.f32 "
        "{%0,%1,%2,%3}, {%4,%5,%6,%7}, {%8,%9}, {%0,%1,%2,%3};\n"
        : "+f"(c[0]), "+f"(c[1]), "+f"(c[2]), "+f"(c[3])
        : "r"(a[0]), "r"(a[1]), "r"(a[2]), "r"(a[3]), "r"(b[0]), "r"(b[1]));
}

// ---------------------------------------------------------------------------
// convert-only: hi = fp16(x)
// ---------------------------------------------------------------------------
__global__ void conv_fp16_kernel(const float* __restrict__ src,
                                 __half* __restrict__ hi)
{
    int i = blockIdx.x * blockDim.x + threadIdx.x;
    float4 v = ((const float4*)src)[i];
    __half h[4];
    h[0] = __float2half_rn(v.x); h[1] = __float2half_rn(v.y);
    h[2] = __float2half_rn(v.z); h[3] = __float2half_rn(v.w);
    ((uint2*)hi)[i] = *(uint2*)h;
}

// ---------------------------------------------------------------------------
// fused: G -> Gh (fp16) AND ghh = fp16(mean_k G)   (single read of G)
// ---------------------------------------------------------------------------
__global__ void gconv_gmean_kernel(const float* __restrict__ G,
                                   __half* __restrict__ Gh,
                                   __half* __restrict__ ghh)
{
    int idx = blockIdx.x * blockDim.x + threadIdx.x;   // over B * (D/4)
    int b  = idx >> 7;
    int ch = idx & 127;
    const float4* gp = (const float4*)(G + (size_t)b * KDIM * DDIM + ch * 4);
    float4 acc = make_float4(0.f, 0.f, 0.f, 0.f);
#pragma unroll
    for (int k = 0; k < KDIM; k++) {
        float4 v = gp[k * (DDIM / 4)];
        __half h[4];
        h[0] = __float2half_rn(v.x); h[1] = __float2half_rn(v.y);
        h[2] = __float2half_rn(v.z); h[3] = __float2half_rn(v.w);
        ((uint2*)Gh)[((size_t)b * KDIM * DDIM + (size_t)k * DDIM) / 4 + ch] = *(uint2*)h;
        acc.x += v.x; acc.y += v.y; acc.z += v.z; acc.w += v.w;
    }
    const float inv = 1.0f / KDIM;
    __half m[4];
    m[0] = __float2half_rn(acc.x * inv); m[1] = __float2half_rn(acc.y * inv);
    m[2] = __float2half_rn(acc.z * inv); m[3] = __float2half_rn(acc.w * inv);
    ((uint2*)ghh)[idx] = *(uint2*)m;
}

// ---------------------------------------------------------------------------
// fp16 tensor-core GEMM. BM=128, BN=128, BK=64, 8 warps (4m x 2n),
// warp tile 32x64 (64 accum regs). 3-stage cp.async pipeline, flattened
// across n-tiles: the pipeline never drains at n-tile boundaries.
// REDUCE=true : out[row] = sum_n relu(acc + Eb[row>>RPB_SHIFT, n]) * wvec[n] (+sc)
//               grid = (M/128), loops all N tiles internally.
// REDUCE=false: out[row,col] = acc + bias[col]; grid = (M/128, N/128).
// ---------------------------------------------------------------------------
constexpr int ASZ = 128 * 72 * 2;     // one A stage (bytes), row stride 72 halves
constexpr int BSZ = 64 * 136 * 2;     // one B stage (bytes), row stride 136 halves
constexpr int SMEM_BYTES = 3 * ASZ + 3 * BSZ + 128 * 2 * 4;
constexpr int NKT = DDIM / 64;        // 8 k-tiles per n-tile

template <int RPB_SHIFT, bool REDUCE>
__global__ void __launch_bounds__(256, 2) mma_gemm(
    const __half* __restrict__ Ah,
    const __half* __restrict__ Bh,
    const float* __restrict__ EbOrBias,
    const float* __restrict__ wvec,
    const float* __restrict__ addsc,
    float* __restrict__ out,
    int N)
{
    extern __shared__ __align__(16) char smraw[];
    float* red = (float*)(smraw + 3 * ASZ + 3 * BSZ);   // [128][2]

    const int tid  = threadIdx.x;
    const int lane = tid & 31;
    const int wid  = tid >> 5;
    const int warp_m = wid & 3;       // 4 warps in M
    const int warp_n = wid >> 2;      // 2 warps in N
    const int lq = lane >> 2, lr = lane & 3;
    const int rb = blockIdx.x * 128;

    const uint32_t uS = (uint32_t)__cvta_generic_to_shared(smraw);
    const uint32_t uA = uS;
    const uint32_t uB = uS + 3 * ASZ;

    // ldmatrix per-lane address components
    const uint32_t a_frag_off =
        (uint32_t)(((warp_m * 32 + (lane & 15)) * 72 + ((lane & 16) >> 1)) * 2);
    const uint32_t b_frag_off =
        (uint32_t)(((lane & 15) * 136 + warp_n * 64 + ((lane & 16) >> 1)) * 2);

    float rs[2][2] = {{0.f, 0.f}, {0.f, 0.f}};
    const int ntiles = REDUCE ? (N >> 7) : 1;
    const int total = ntiles * NKT;

    // stage global tile g (nt = g/NKT, kt = g%NKT) into buffer g%3.
    // A: 128x64 halves = 4 chunks/thread; B: 64x128 halves = 4 chunks/thread.
    auto stageg = [&](int g) {
        const int nt = g / NKT;
        const int kt = g - nt * NKT;
        const int cb = REDUCE ? (nt << 7) : ((int)blockIdx.y << 7);
        const int koff = kt << 6;
        const int buf = g % 3;
        const uint32_t adst0 = uA + (uint32_t)(buf * ASZ);
        const uint32_t bdst0 = uB + (uint32_t)(buf * BSZ);
#pragma unroll
        for (int cc = 0; cc < 4; cc++) {
            int cid = tid + cc * 256;
            int am = cid >> 3, ak = (cid & 7) << 3;
            cp16(adst0 + (uint32_t)((am * 72 + ak) * 2),
                 Ah + (size_t)(rb + am) * DDIM + koff + ak);
            int bk = cid >> 4, bn = (cid & 15) << 3;
            cp16(bdst0 + (uint32_t)((bk * 136 + bn) * 2),
                 Bh + (size_t)(koff + bk) * N + cb + bn);
        }
    };

    float c[2][8][4] = {};

    stageg(0); cp_commit();
    if (total > 1) stageg(1);
    cp_commit();

    for (int g = 0; g < total; g++) {
        cp_wait1();
        __syncthreads();
        if (g + 2 < total) stageg(g + 2);
        cp_commit();

        const int buf = g % 3;
        const uint32_t Ahb = uA + (uint32_t)(buf * ASZ) + a_frag_off;
        const uint32_t Bhb = uB + (uint32_t)(buf * BSZ) + b_frag_off;

#pragma unroll
        for (int kk = 0; kk < 64; kk += 16) {
            unsigned ah[2][4], bh[8][2];
#pragma unroll
            for (int mi = 0; mi < 2; mi++)
                ldsm_x4(ah[mi][0], ah[mi][1], ah[mi][2], ah[mi][3],
                        Ahb + (uint32_t)((mi * 16 * 72 + kk) * 2));
#pragma unroll
            for (int gg = 0; gg < 4; gg++)
                ldsm_x4_t(bh[2*gg][0], bh[2*gg][1], bh[2*gg+1][0], bh[2*gg+1][1],
                          Bhb + (uint32_t)((kk * 136 + gg * 16) * 2));
#pragma unroll
            for (int mi = 0; mi < 2; mi++)
#pragma unroll
                for (int ni = 0; ni < 8; ni++)
                    mma16816(c[mi][ni], ah[mi], bh[ni]);
        }

        // n-tile boundary: epilogue (register-only for REDUCE; loads for
        // tiles g+1, g+2 remain in flight behind it)
        if ((g + 1) % NKT == 0) {
            const int nt = g / NKT;
            const int cb = REDUCE ? (nt << 7) : ((int)blockIdx.y << 7);
            if (REDUCE) {
#pragma unroll
                for (int mi = 0; mi < 2; mi++) {
                    int row0 = rb + warp_m * 32 + mi * 16 + lq;
                    int row1 = row0 + 8;
                    const float* Eb0 = EbOrBias + (size_t)(row0 >> RPB_SHIFT) * N;
                    const float* Eb1 = EbOrBias + (size_t)(row1 >> RPB_SHIFT) * N;
#pragma unroll
                    for (int ni = 0; ni < 8; ni++) {
                        int col = cb + warp_n * 64 + ni * 8 + lr * 2;
                        float2 e0 = *(const float2*)&Eb0[col];
                        float2 e1 = *(const float2*)&Eb1[col];
                        float2 wv = *(const float2*)&wvec[col];
                        rs[mi][0] += fmaxf(c[mi][ni][0] + e0.x, 0.f) * wv.x
                                   + fmaxf(c[mi][ni][1] + e0.y, 0.f) * wv.y;
                        rs[mi][1] += fmaxf(c[mi][ni][2] + e1.x, 0.f) * wv.x
                                   + fmaxf(c[mi][ni][3] + e1.y, 0.f) * wv.y;
                    }
                }
            } else {
#pragma unroll
                for (int mi = 0; mi < 2; mi++) {
                    int row0 = rb + warp_m * 32 + mi * 16 + lq;
                    int row1 = row0 + 8;
#pragma unroll
                    for (int ni = 0; ni < 8; ni++) {
                        int col = cb + warp_n * 64 + ni * 8 + lr * 2;
                        float2 bv = *(const float2*)&EbOrBias[col];
                        float2 o0, o1;
                        o0.x = c[mi][ni][0] + bv.x; o0.y = c[mi][ni][1] + bv.y;
                        o1.x = c[mi][ni][2] + bv.x; o1.y = c[mi][ni][3] + bv.y;
                        *(float2*)&out[(size_t)row0 * N + col] = o0;
                        *(float2*)&out[(size_t)row1 * N + col] = o1;
                    }
                }
            }
            // reset accumulators for the next n-tile
#pragma unroll
            for (int mi = 0; mi < 2; mi++)
#pragma unroll
                for (int ni = 0; ni < 8; ni++)
#pragma unroll
                    for (int e = 0; e < 4; e++) c[mi][ni][e] = 0.f;
        }
    }

    if (REDUCE) {
        // reduce across the 4 lanes sharing each row, then across warp_n
#pragma unroll
        for (int mi = 0; mi < 2; mi++)
#pragma unroll
            for (int h = 0; h < 2; h++) {
                float s = rs[mi][h];
                s += __shfl_xor_sync(0xffffffffu, s, 1);
                s += __shfl_xor_sync(0xffffffffu, s, 2);
                if (lr == 0)
                    red[(warp_m * 32 + mi * 16 + h * 8 + lq) * 2 + warp_n] = s;
            }
        __syncthreads();
        if (tid < 128) {
            float addv = addsc ? *addsc : 0.f;
            out[rb + tid] = red[tid * 2 + 0] + red[tid * 2 + 1] + addv;
        }
    }
}

// ---------------------------------------------------------------------------
// K4: per-b softmax over T=32 then x_hat = sum_t alpha_t * Xh[b,t,:] -> fp16
// ---------------------------------------------------------------------------
__global__ void softmax_xhat_kernel(const float* __restrict__ e,
                                    const __half* __restrict__ Xh,
                                    __half* __restrict__ xh)
{
    int b = blockIdx.x;
    __shared__ float alpha[TDIM];
    int tid = threadIdx.x;   // 128 threads
    if (tid < 32) {
        float v = e[b * TDIM + tid];
        float m = v;
#pragma unroll
        for (int off = 16; off >= 1; off >>= 1)
            m = fmaxf(m, __shfl_xor_sync(0xffffffffu, m, off));
        float ex = __expf(v - m);
        float s = ex;
#pragma unroll
        for (int off = 16; off >= 1; off >>= 1)
            s += __shfl_xor_sync(0xffffffffu, s, off);
        alpha[tid] = ex / s;
    }
    __syncthreads();
    const __half* Xb = Xh + (size_t)b * TDIM * DDIM + tid * 4;
    float s0 = 0.f, s1 = 0.f, s2 = 0.f, s3 = 0.f;
#pragma unroll
    for (int t = 0; t < TDIM; t++) {
        uint2 raw = *(const uint2*)&Xb[t * DDIM];
        __half2 p0 = *(__half2*)&raw.x;
        __half2 p1 = *(__half2*)&raw.y;
        float a = alpha[t];
        s0 += a * __low2float(p0);  s1 += a * __high2float(p0);
        s2 += a * __low2float(p1);  s3 += a * __high2float(p1);
    }
    __half hh[4];
    hh[0] = __float2half_rn(s0); hh[1] = __float2half_rn(s1);
    hh[2] = __float2half_rn(s2); hh[3] = __float2half_rn(s3);
    ((uint2*)xh)[((size_t)b * DDIM + tid * 4) >> 2] = *(uint2*)hh;
}

// ---------------------------------------------------------------------------
extern "C" void kernel_launch(void* const* d_in, const int* in_sizes, int n_in,
                              void* d_out, int out_size)
{
    const float* X  = (const float*)d_in[0];
    const float* G  = (const float*)d_in[1];
    const float* W1 = (const float*)d_in[2];
    const float* b1 = (const float*)d_in[3];
    const float* w2 = (const float*)d_in[4];
    // d_in[5] = b2: softmax shift-invariant, unused
    const float* M1 = (const float*)d_in[6];
    const float* c1 = (const float*)d_in[7];
    const float* m2 = (const float*)d_in[8];
    const float* c2 = (const float*)d_in[9];
    float* out = (float*)d_out;

    float *E1, *E2, *ebuf;
    cudaGetSymbolAddress((void**)&E1,   E1_buf);
    cudaGetSymbolAddress((void**)&E2,   E2_buf);
    cudaGetSymbolAddress((void**)&ebuf, e_buf);

    __half *Xh, *Gh, *W1h, *M1h, *ghh, *xhh;
    cudaGetSymbolAddress((void**)&Xh,  Xh_buf);
    cudaGetSymbolAddress((void**)&Gh,  Gh_buf);
    cudaGetSymbolAddress((void**)&W1h, W1h_buf);
    cudaGetSymbolAddress((void**)&M1h, M1h_buf);
    cudaGetSymbolAddress((void**)&ghh, ghh_buf);
    cudaGetSymbolAddress((void**)&xhh, xhh_buf);

    cudaFuncSetAttribute((const void*)mma_gemm<5, true>,
                         cudaFuncAttributeMaxDynamicSharedMemorySize, SMEM_BYTES);
    cudaFuncSetAttribute((const void*)mma_gemm<4, true>,
                         cudaFuncAttributeMaxDynamicSharedMemorySize, SMEM_BYTES);
    cudaFuncSetAttribute((const void*)mma_gemm<0, false>,
                         cudaFuncAttributeMaxDynamicSharedMemorySize, SMEM_BYTES);

    // [0] convert X -> fp16
    conv_fp16_kernel<<<(BDIM * TDIM * DDIM / 4) / 256, 256>>>(X, Xh);
    // [1] convert W1 -> fp16
    conv_fp16_kernel<<<(2 * DDIM * HDIM / 4) / 256, 256>>>(W1, W1h);
    // [2] fused: G -> Gh, ghh = mean_k G (single read of G)
    gconv_gmean_kernel<<<(BDIM * DDIM / 4) / 256, 256>>>(G, Gh, ghh);
    // [3] K2: E1 = g_hat @ W1[:512] + b1   (4096 x 1024)
    mma_gemm<0, false><<<dim3(BDIM / 128, HDIM / 128), 256, SMEM_BYTES>>>(
        ghh, W1h, b1, nullptr, nullptr, E1, HDIM);
    // [4] convert M1 -> fp16
    conv_fp16_kernel<<<(2 * DDIM * H2DIM / 4) / 256, 256>>>(M1, M1h);
    // [5] K3: e[b,t] = sum_h relu( X@W1[512:] + E1 ) * w2   (M = 131072)
    mma_gemm<5, true><<<(BDIM * TDIM) / 128, 256, SMEM_BYTES>>>(
        Xh, W1h + (size_t)DDIM * HDIM, E1, w2, nullptr, ebuf, HDIM);
    // [6] softmax over T + x_hat -> fp16
    softmax_xhat_kernel<<<BDIM, 128>>>(ebuf, Xh, xhh);
    // [7] K5: E2 = x_hat @ M1[:512] + c1   (4096 x 2048)
    mma_gemm<0, false><<<dim3(BDIM / 128, H2DIM / 128), 256, SMEM_BYTES>>>(
        xhh, M1h, c1, nullptr, nullptr, E2, H2DIM);
    // [8] K6: logits = sum_j relu( G@M1[512:] + E2 ) * m2 + c2  (M = 65536)
    mma_gemm<4, true><<<(BDIM * KDIM) / 128, 256, SMEM_BYTES>>>(
        Gh, M1h + (size_t)DDIM * H2DIM, E2, m2, c2, out, H2DIM);
}